// round 17
// baseline (speedup 1.0000x reference)
#include <cuda_runtime.h>
#include <cuda_bf16.h>
#include <cstdint>

#define NQ 8192
#define NK 8192
#define KEEP 4096

// Concatenated float32 output offsets
#define OFF_COORDS 0
#define OFF_VOX    16384
#define OFF_KIMP   98304
#define OFF_IMP    102400

#define SQRT3 1.7320508075688772f

typedef unsigned long long u64;
typedef unsigned int u32;

// ---- persistent device scratch (allocation-free) ----
__device__ __align__(16) float g_kz[2][NK];   // key z-coord, grouped by batch, stable order
__device__ __align__(16) float g_ky[2][NK];   // key y-coord
__device__ __align__(16) float g_kx[2][NK];   // key x-coord
__device__ int    g_kcnt[2];
__device__ int    g_qidx[2][NQ];              // query indices grouped by batch, stable
__device__ int    g_qcnt[2];
__device__ int    g_bc[64];                   // per-block batch-0 counts

// ---- packed f32x2 helpers (IEEE per-lane, bit-identical to scalar) ----
__device__ __forceinline__ u64 mul2(u64 a, u64 b) {
    u64 d; asm("mul.rn.f32x2 %0, %1, %2;" : "=l"(d) : "l"(a), "l"(b)); return d;
}
__device__ __forceinline__ u64 fma2(u64 a, u64 b, u64 c) {
    u64 d; asm("fma.rn.f32x2 %0, %1, %2, %3;" : "=l"(d) : "l"(a), "l"(b), "l"(c)); return d;
}
__device__ __forceinline__ u64 pack2(float v) {
    u64 d; asm("mov.b64 %0, {%1, %1};" : "=l"(d) : "f"(v)); return d;
}
__device__ __forceinline__ float2 unpack2(u64 v) {
    float2 f; asm("mov.b64 {%0, %1}, %2;" : "=f"(f.x), "=f"(f.y) : "l"(v)); return f;
}

// XLA EmitFastTanh (Eigen ptanh<float>) — exact coefficients, clamp, small-x path.
__device__ __forceinline__ float tanh_xla(float x) {
    float ax = fabsf(x);
    float xc = fminf(fmaxf(x, -7.90531110763549805f), 7.90531110763549805f);
    float x2 = xc * xc;
    float p = fmaf(x2, -2.76076847742355e-16f, 2.00018790482477e-13f);
    p = fmaf(x2, p, -8.60467152213735e-11f);
    p = fmaf(x2, p, 5.12229709037114e-08f);
    p = fmaf(x2, p, 1.48572235717979e-05f);
    p = fmaf(x2, p, 6.37261928875436e-04f);
    p = fmaf(x2, p, 4.89352455891786e-03f);
    p = xc * p;
    float q = fmaf(x2, 1.19825839466702e-06f, 1.18534705686654e-04f);
    q = fmaf(x2, q, 2.26843463243900e-03f);
    q = fmaf(x2, q, 4.89352518554385e-03f);
    float r = p / q;
    return (ax < 0.0004f) ? x : r;
}

// ---- partition phase 1: per-block batch-0 counts (64 blocks x 256 threads) ----
__global__ __launch_bounds__(256) void count_kernel(
    const int4* __restrict__ vc, const float4* __restrict__ keys)
{
    __shared__ int ws[8];
    int b = blockIdx.x, t = threadIdx.x;
    int flag;
    if (b < 32) flag = (keys[b * 256 + t].x == 0.0f) ? 1 : 0;
    else        flag = (vc[(b - 32) * 256 + t].x == 0) ? 1 : 0;
    unsigned bal = __ballot_sync(0xffffffffu, flag);
    if ((t & 31) == 0) ws[t >> 5] = __popc(bal);
    __syncthreads();
    if (t == 0) {
        int s = 0;
        #pragma unroll
        for (int i = 0; i < 8; i++) s += ws[i];
        g_bc[b] = s;
    }
}

// ---- partition phase 2: stable scatter to SoA (64 blocks x 256 threads) ----
__global__ __launch_bounds__(256) void scatter_kernel(
    const int4* __restrict__ vc, const float4* __restrict__ keys)
{
    __shared__ int ws[8];
    __shared__ int s_pre0, s_tot0;
    int b = blockIdx.x, t = threadIdx.x;
    bool isKey = (b < 32);
    int c = isKey ? b : b - 32;
    int grp = isKey ? 0 : 32;

    if (t < 32) {
        int v = g_bc[grp + t];
        int x = v;
        #pragma unroll
        for (int o = 1; o < 32; o <<= 1) {
            int y = __shfl_up_sync(0xffffffffu, x, o);
            if (t >= o) x += y;
        }
        if (t == c)  s_pre0 = x - v;
        if (t == 31) s_tot0 = x;
    }
    __syncthreads();

    int i = c * 256 + t;
    int flag;
    float4 kv; int4 qv;
    if (isKey) { kv = keys[i]; flag = (kv.x == 0.0f) ? 1 : 0; }
    else       { qv = vc[i];   flag = (qv.x == 0) ? 1 : 0; }

    unsigned bal = __ballot_sync(0xffffffffu, flag);
    int lane = t & 31, w = t >> 5;
    int lpre = __popc(bal & ((1u << lane) - 1u));
    if (lane == 0) ws[w] = __popc(bal);
    __syncthreads();
    int wpre = 0;
    for (int j = 0; j < w; j++) wpre += ws[j];

    int pos0 = s_pre0 + wpre + lpre;
    int pos1 = i - pos0;
    if (isKey) {
        int bb = flag ? 0 : 1;
        int pp = flag ? pos0 : pos1;
        g_kz[bb][pp] = kv.y;
        g_ky[bb][pp] = kv.z;
        g_kx[bb][pp] = kv.w;
        if (t == 0 && c == 0) { g_kcnt[0] = s_tot0; g_kcnt[1] = NK - s_tot0; }
    } else {
        if (flag) g_qidx[0][pos0] = i; else g_qidx[1][pos1] = i;
        if (t == 0 && c == 0) { g_qcnt[0] = s_tot0; g_qcnt[1] = NQ - s_tot0; }
    }
}

// ---- attention: 2 queries per group; 4 warps per group, each sweeping a
//      128-aligned key chunk lane-strided; fixed-order smem combine. ----
#define QPW 2

__global__ __launch_bounds__(256) void attn_kernel(
    const int4*  __restrict__ vc,
    const float* __restrict__ w1,
    const float* __restrict__ b1,
    const float* __restrict__ w2,
    const float* __restrict__ b2,
    float*       __restrict__ imp_out)
{
    __shared__ float  smaxs[2][4][QPW];
    __shared__ float4 saccs[2][4][QPW];

    int warp = threadIdx.x >> 5, lane = threadIdx.x & 31;
    int g = warp >> 2;          // group within block (0..1)
    int h = warp & 3;           // chunk (0..3)

    int qc0 = g_qcnt[0], qc1 = g_qcnt[1];
    int ngrp0 = (qc0 + QPW - 1) / QPW;
    int ngrp1 = (qc1 + QPW - 1) / QPW;
    int ntot = ngrp0 + ngrp1;

    int G = blockIdx.x * 2 + g;
    bool valid = (G < ntot);
    int b = 0, gg = 0, qc = qc0;
    if (valid) {
        if (G < ngrp0) { b = 0; gg = G;         qc = qc0; }
        else           { b = 1; gg = G - ngrp0; qc = qc1; }
    }
    if (qc == 0) valid = false;

    int qi[QPW];
    float qzs[QPW], qys[QPW], qxs[QPW];
    u64 qz2[QPW], qy2[QPW], qx2[QPW];
    if (valid) {
        #pragma unroll
        for (int i = 0; i < QPW; i++) {
            int idx = QPW * gg + i;
            qi[i] = g_qidx[b][idx < qc ? idx : qc - 1];
            int4 q = vc[qi[i]];
            qzs[i] = (float)q.y; qys[i] = (float)q.z; qxs[i] = (float)q.w;
            qz2[i] = pack2(qzs[i]); qy2[i] = pack2(qys[i]); qx2[i] = pack2(qxs[i]);
        }
    }

    const ulonglong2* z2 = (const ulonglong2*)g_kz[b];
    const ulonglong2* y2 = (const ulonglong2*)g_ky[b];
    const ulonglong2* x2 = (const ulonglong2*)g_kx[b];
    const float* kzs = g_kz[b];
    const float* kys = g_ky[b];
    const float* kxs = g_kx[b];
    int kc = valid ? g_kcnt[b] : 0;

    // chunk bounds: 128-aligned start, last chunk takes remainder
    int ck = ((kc + 511) >> 9) << 7;     // ceil(kc/512)*128
    int cs = h * ck; if (cs > kc) cs = kc;
    int ce = cs + ck; if (ce > kc) ce = kc;
    int nfull = (ce - cs) & ~127;

    // ---- pass 1: chunk-local max in dot-space ----
    float mxd[QPW];
    #pragma unroll
    for (int i = 0; i < QPW; i++) mxd[i] = -3.0e38f;

    for (int base = cs; base < cs + nfull; base += 128) {
        int m2 = (base >> 2) + lane;
        ulonglong2 zz = z2[m2], yy = y2[m2], xx = x2[m2];
        #pragma unroll
        for (int i = 0; i < QPW; i++) {
            u64 d01 = fma2(qx2[i], xx.x, fma2(qy2[i], yy.x, mul2(qz2[i], zz.x)));
            u64 d23 = fma2(qx2[i], xx.y, fma2(qy2[i], yy.y, mul2(qz2[i], zz.y)));
            float2 a = unpack2(d01), c = unpack2(d23);
            mxd[i] = fmaxf(mxd[i], fmaxf(fmaxf(a.x, a.y), fmaxf(c.x, c.y)));
        }
    }
    for (int m = cs + nfull + lane; m < ce; m += 32) {
        float kz = kzs[m], ky = kys[m], kx = kxs[m];
        #pragma unroll
        for (int i = 0; i < QPW; i++) {
            float d = fmaf(qxs[i], kx, fmaf(qys[i], ky, qzs[i] * kz));
            mxd[i] = fmaxf(mxd[i], d);
        }
    }
    #pragma unroll
    for (int o = 16; o; o >>= 1)
        #pragma unroll
        for (int i = 0; i < QPW; i++)
            mxd[i] = fmaxf(mxd[i], __shfl_xor_sync(0xffffffffu, mxd[i], o));
    if (lane == 0) {
        #pragma unroll
        for (int i = 0; i < QPW; i++) smaxs[g][h][i] = mxd[i];
    }
    __syncthreads();

    float mx[QPW], thr[QPW];
    #pragma unroll
    for (int i = 0; i < QPW; i++) {
        float gm = fmaxf(fmaxf(smaxs[g][0][i], smaxs[g][1][i]),
                         fmaxf(smaxs[g][2][i], smaxs[g][3][i]));
        mx[i]  = gm / SQRT3;              // == max(dot/sqrt3), monotone
        thr[i] = (mx[i] - 88.0f) * SQRT3; // conservative dot-space prefilter
    }

    // ---- pass 2 (fused): chunk-local sum of exp + unnormalized weighted coords ----
    float sum[QPW], c0[QPW], c1[QPW], c2[QPW];
    #pragma unroll
    for (int i = 0; i < QPW; i++) { sum[i] = 0; c0[i] = 0; c1[i] = 0; c2[i] = 0; }

    for (int base = cs; base < cs + nfull; base += 128) {
        int m2 = (base >> 2) + lane;
        ulonglong2 zz = z2[m2], yy = y2[m2], xx = x2[m2];
        #pragma unroll
        for (int i = 0; i < QPW; i++) {
            u64 d01 = fma2(qx2[i], xx.x, fma2(qy2[i], yy.x, mul2(qz2[i], zz.x)));
            u64 d23 = fma2(qx2[i], xx.y, fma2(qy2[i], yy.y, mul2(qz2[i], zz.y)));
            float2 a = unpack2(d01), c = unpack2(d23);
            float md = fmaxf(fmaxf(a.x, a.y), fmaxf(c.x, c.y));
            if (md > thr[i]) {             // rare path
                float ds[4] = {a.x, a.y, c.x, c.y};
                float2 kzp0 = unpack2(zz.x), kzp1 = unpack2(zz.y);
                float2 kyp0 = unpack2(yy.x), kyp1 = unpack2(yy.y);
                float2 kxp0 = unpack2(xx.x), kxp1 = unpack2(xx.y);
                float kzv[4] = {kzp0.x, kzp0.y, kzp1.x, kzp1.y};
                float kyv[4] = {kyp0.x, kyp0.y, kyp1.x, kyp1.y};
                float kxv[4] = {kxp0.x, kxp0.y, kxp1.x, kxp1.y};
                #pragma unroll
                for (int e = 0; e < 4; e++) {
                    float d = ds[e];
                    if (d > thr[i]) {
                        float s = d / SQRT3;
                        float t2 = s - mx[i];
                        if (t2 > -80.0f) {
                            float aa = expf(t2);
                            sum[i] += aa;
                            c0[i] = fmaf(aa, kzv[e], c0[i]);
                            c1[i] = fmaf(aa, kyv[e], c1[i]);
                            c2[i] = fmaf(aa, kxv[e], c2[i]);
                        }
                    }
                }
            }
        }
    }
    for (int m = cs + nfull + lane; m < ce; m += 32) {
        float kz = kzs[m], ky = kys[m], kx = kxs[m];
        #pragma unroll
        for (int i = 0; i < QPW; i++) {
            float d = fmaf(qxs[i], kx, fmaf(qys[i], ky, qzs[i] * kz));
            if (d > thr[i]) {
                float s = d / SQRT3;
                float t2 = s - mx[i];
                if (t2 > -80.0f) {
                    float aa = expf(t2);
                    sum[i] += aa;
                    c0[i] = fmaf(aa, kz, c0[i]);
                    c1[i] = fmaf(aa, ky, c1[i]);
                    c2[i] = fmaf(aa, kx, c2[i]);
                }
            }
        }
    }
    #pragma unroll
    for (int o = 16; o; o >>= 1)
        #pragma unroll
        for (int i = 0; i < QPW; i++) {
            sum[i] += __shfl_xor_sync(0xffffffffu, sum[i], o);
            c0[i]  += __shfl_xor_sync(0xffffffffu, c0[i], o);
            c1[i]  += __shfl_xor_sync(0xffffffffu, c1[i], o);
            c2[i]  += __shfl_xor_sync(0xffffffffu, c2[i], o);
        }
    if (lane == 0) {
        #pragma unroll
        for (int i = 0; i < QPW; i++)
            saccs[g][h][i] = make_float4(sum[i], c0[i], c1[i], c2[i]);
    }
    __syncthreads();

    // ---- chunk-0 warp: fixed-order combine + MLP + logistic ----
    if (valid && h == 0) {
        #pragma unroll
        for (int i = 0; i < QPW; i++) {
            if (lane == i) {
                float S = 0, C0 = 0, C1 = 0, C2 = 0;
                #pragma unroll
                for (int w = 0; w < 4; w++) {
                    float4 a = saccs[g][w][i];
                    S += a.x; C0 += a.y; C1 += a.z; C2 += a.w;
                }
                C0 /= S; C1 /= S; C2 /= S;
                float logit = 0.0f;
                #pragma unroll
                for (int j = 0; j < 32; j++) {
                    float hh = C0 * w1[j];
                    hh = fmaf(C1, w1[32 + j], hh);
                    hh = fmaf(C2, w1[64 + j], hh);
                    hh = hh + b1[j];
                    hh = fmaxf(hh, 0.0f);
                    logit = fmaf(hh, w2[j], logit);
                }
                logit = logit + b2[0];
                imp_out[qi[i]] = 0.5f + 0.5f * tanh_xla(0.5f * logit);
            }
        }
    }
}

// ---- rank: 2 voxels per pair; 2 warps per pair each sweeping half the t-range;
//      split-loop stable counting on float bits; exact integer combine. ----
// rank(i) = #{j<i : v_j <= v_i} + #{j>i : v_j < v_i}
__global__ __launch_bounds__(256) void rank_kernel(
    const float* __restrict__ imp,
    const int*   __restrict__ vc,
    const float* __restrict__ voxels,
    float*       __restrict__ out)
{
    __shared__ int scnt[4][2][2];

    int warp = threadIdx.x >> 5, lane = threadIdx.x & 31;
    int p = warp >> 1;          // pair within block (0..3)
    int h = warp & 1;           // half (0..1)

    int P = blockIdx.x * 4 + p; // global pair index
    int i0 = 2 * P, i1 = i0 + 1;

    const u32*   ib  = (const u32*)imp;
    const uint4* ib4 = (const uint4*)imp;
    u32 my0 = ib[i0], my1 = ib[i1];

    int tA = i0 >> 7;                   // t covers j in [128t, 128t+128); 64 t total
    int ts = h * 32, te = ts + 32;
    int cnt0 = 0, cnt1 = 0;

    // region A: t < tA  (all j < i0)
    int teA = tA < te ? tA : te;
    #pragma unroll 4
    for (int t = ts; t < teA; t++) {
        uint4 v = ib4[t * 32 + lane];
        cnt0 += (int)(v.x <= my0) + (int)(v.y <= my0) + (int)(v.z <= my0) + (int)(v.w <= my0);
        cnt1 += (int)(v.x <= my1) + (int)(v.y <= my1) + (int)(v.z <= my1) + (int)(v.w <= my1);
    }
    // boundary t == tA (contains j == i0 and j == i1)
    if (tA >= ts && tA < te) {
        uint4 v = ib4[tA * 32 + lane];
        int j = tA * 128 + lane * 4;
        u32 e[4] = {v.x, v.y, v.z, v.w};
        #pragma unroll
        for (int k = 0; k < 4; k++) {
            cnt0 += (j + k < i0) ? (int)(e[k] <= my0) : (int)(e[k] < my0);
            cnt1 += (j + k < i1) ? (int)(e[k] <= my1) : (int)(e[k] < my1);
        }
    }
    // region B: t > tA  (all j > i1)
    int tsB = (tA + 1) > ts ? (tA + 1) : ts;
    #pragma unroll 4
    for (int t = tsB; t < te; t++) {
        uint4 v = ib4[t * 32 + lane];
        cnt0 += (int)(v.x < my0) + (int)(v.y < my0) + (int)(v.z < my0) + (int)(v.w < my0);
        cnt1 += (int)(v.x < my1) + (int)(v.y < my1) + (int)(v.z < my1) + (int)(v.w < my1);
    }

    #pragma unroll
    for (int o = 16; o; o >>= 1) {
        cnt0 += __shfl_xor_sync(0xffffffffu, cnt0, o);
        cnt1 += __shfl_xor_sync(0xffffffffu, cnt1, o);
    }
    if (lane == 0) { scnt[p][h][0] = cnt0; scnt[p][h][1] = cnt1; }
    __syncthreads();

    if (h == 0) {
        int tot0 = scnt[p][0][0] + scnt[p][1][0];
        int tot1 = scnt[p][0][1] + scnt[p][1][1];
        if (tot0 >= KEEP) {
            int row = tot0 - KEEP;
            if (lane < 20) out[OFF_VOX + row * 20 + lane] = voxels[i0 * 20 + lane];
            if (lane < 4)  out[OFF_COORDS + row * 4 + lane] = (float)vc[i0 * 4 + lane];
            if (lane == 0) out[OFF_KIMP + row] = imp[i0];
        }
        if (tot1 >= KEEP) {
            int row = tot1 - KEEP;
            if (lane < 20) out[OFF_VOX + row * 20 + lane] = voxels[i1 * 20 + lane];
            if (lane < 4)  out[OFF_COORDS + row * 4 + lane] = (float)vc[i1 * 4 + lane];
            if (lane == 0) out[OFF_KIMP + row] = imp[i1];
        }
    }
}

extern "C" void kernel_launch(void* const* d_in, const int* in_sizes, int n_in,
                              void* d_out, int out_size) {
    const int*   vc     = (const int*)d_in[0];
    const float* keys   = (const float*)d_in[1];
    const float* voxels = (const float*)d_in[2];
    const float* w1     = (const float*)d_in[3];
    const float* b1     = (const float*)d_in[4];
    const float* w2     = (const float*)d_in[5];
    const float* b2     = (const float*)d_in[6];
    float* out = (float*)d_out;
    float* imp = out + OFF_IMP;

    count_kernel<<<64, 256>>>((const int4*)vc, (const float4*)keys);
    scatter_kernel<<<64, 256>>>((const int4*)vc, (const float4*)keys);
    // groups <= NQ/2 + 1 = 4097; 2 groups per block
    attn_kernel<<<2049, 256>>>((const int4*)vc, w1, b1, w2, b2, imp);
    // NQ/2 = 4096 pairs; 4 pairs per block
    rank_kernel<<<1024, 256>>>(imp, vc, voxels, out);
}